// round 12
// baseline (speedup 1.0000x reference)
#include <cuda_runtime.h>
#include <math.h>

#define NREG 36
#define EMBD 1024
#define SIMD 16
#define HIDD 32
#define NKER 8

// Precomputed folded constants (prep_kernel -> main kernel)
__device__ float g_W1f[SIMD * HIDD];  // gsum · w1n^T folded: [d][hh]
__device__ float g_w2s[HIDD];         // weight-normed out2 row / 36
__device__ float g_b1[HIDD];

__global__ void prep_kernel(const float* __restrict__ gcn_w,
                            const float* __restrict__ out1_v, const float* __restrict__ out1_g,
                            const float* __restrict__ out1_b, const float* __restrict__ out2_v,
                            const float* __restrict__ out2_g, const float* __restrict__ out2_b,
                            float* __restrict__ out, int Bn)
{
    __shared__ float gs[SIMD * HIDD];
    __shared__ float w1[HIDD * HIDD];
    __shared__ float b2v;
    const int tid = threadIdx.x;  // 512
    {
        float a = 0.f;
        #pragma unroll
        for (int k = 0; k < NKER; k++) a += gcn_w[k * SIMD * HIDD + tid];
        gs[tid] = a;
    }
    if (tid < HIDD) {
        float ss = 0.f;
        #pragma unroll
        for (int h = 0; h < HIDD; h++) { float v = out1_v[tid * HIDD + h]; ss += v * v; }
        const float sc = out1_g[tid] / (sqrtf(ss) + 1e-12f);
        #pragma unroll
        for (int h = 0; h < HIDD; h++) w1[tid * HIDD + h] = out1_v[tid * HIDD + h] * sc;
        g_b1[tid] = out1_b[tid];
    }
    if (tid == 32) {
        float ss = 0.f;
        #pragma unroll
        for (int h = 0; h < HIDD; h++) { float v = out2_v[h]; ss += v * v; }
        const float sc = out2_g[0] / (sqrtf(ss) + 1e-12f);
        #pragma unroll
        for (int h = 0; h < HIDD; h++) g_w2s[h] = out2_v[h] * sc * (1.0f / 36.0f);
        b2v = out2_b[0];
    }
    __syncthreads();
    {
        const int d = tid >> 5, hh = tid & 31;
        float acc = 0.f;
        #pragma unroll
        for (int h = 0; h < HIDD; h++)
            acc = fmaf(gs[d * HIDD + h], w1[hh * HIDD + h], acc);
        g_W1f[d * HIDD + hh] = acc;
    }
    // init out[b] = b2 (chunk CTAs accumulate partial sums on top via atomicAdd)
    for (int i = tid; i < Bn; i += 512) out[i] = b2v;
}

__device__ __forceinline__ void dot3(float& q, float& n, float& x, const float4 a, const float4 c) {
    q = fmaf(a.x, a.x, q); q = fmaf(a.y, a.y, q); q = fmaf(a.z, a.z, q); q = fmaf(a.w, a.w, q);
    n = fmaf(c.x, c.x, n); n = fmaf(c.y, c.y, n); n = fmaf(c.z, c.z, n); n = fmaf(c.w, c.w, n);
    x = fmaf(a.x, c.x, x); x = fmaf(a.y, c.y, x); x = fmaf(a.z, c.z, x); x = fmaf(a.w, c.w, x);
}

// One CTA per 12-row chunk (3 chunks/batch): grid (3, Bn). R5's depth-4
// continuous pipeline verbatim, just 3 row-iterations per warp. Finer work
// units -> 4.15 waves with a tiny tail instead of 1.54 waves with a 54% tail.
__global__ void __launch_bounds__(128, 10)
simgsmn_main(const float* __restrict__ inp1, const float* __restrict__ inp2,
             float* __restrict__ out)
{
    __shared__ float sv[12 * SIMD];
    __shared__ float W1fs[SIMD * HIDD];
    __shared__ float w2ss[HIDD];
    __shared__ float b1s[HIDD];
    __shared__ float red[4];
    const int tid  = threadIdx.x;
    const int w    = tid >> 5;
    const int lane = tid & 31;
    const int g    = lane >> 2;     // group owns sim blocks {2g, 2g+1}
    const int c4   = lane & 3;
    const int ch   = blockIdx.x;    // chunk 0..2
    const int b    = blockIdx.y;

    #pragma unroll
    for (int r = 0; r < 4; r++) W1fs[tid + r * 128] = g_W1f[tid + r * 128];
    if (tid < HIDD) { w2ss[tid] = g_w2s[tid]; b1s[tid] = g_b1[tid]; }

    // warp w streams rows (ch*12 + w + 4*ii), ii = 0..2; row stride 4 rows = 1024 float4
    const float4* p1 = reinterpret_cast<const float4*>(inp1)
                     + (size_t)b * (NREG * EMBD / 4) + (ch * 12 + w) * 256 + g * 32 + c4;
    const float4* p2 = reinterpret_cast<const float4*>(inp2)
                     + (size_t)b * (NREG * EMBD / 4) + (ch * 12 + w) * 256 + g * 32 + c4;

    float4 A0 = __ldcs(p1 +  0), C0 = __ldcs(p2 +  0);
    float4 A1 = __ldcs(p1 +  4), C1 = __ldcs(p2 +  4);
    float4 A2 = __ldcs(p1 +  8), C2 = __ldcs(p2 +  8);
    float4 A3 = __ldcs(p1 + 12), C3 = __ldcs(p2 + 12);

    #pragma unroll 1
    for (int ii = 0; ii < 3; ii++) {
        const int i = w + 4 * ii;          // local row within the 12-row chunk
        const float4* np1 = (ii < 2) ? (p1 + 1024) : p1;  // clamp: last iter reloads (discarded)
        const float4* np2 = (ii < 2) ? (p2 + 1024) : p2;
        float aq0 = 0.f, an0 = 0.f, ax0 = 0.f, aq1 = 0.f, an1 = 0.f, ax1 = 0.f;

        { float4 a = A0, c = C0; A0 = __ldcs(p1 + 16); C0 = __ldcs(p2 + 16); dot3(aq0, an0, ax0, a, c); }
        { float4 a = A1, c = C1; A1 = __ldcs(p1 + 20); C1 = __ldcs(p2 + 20); dot3(aq0, an0, ax0, a, c); }
        { float4 a = A2, c = C2; A2 = __ldcs(p1 + 24); C2 = __ldcs(p2 + 24); dot3(aq0, an0, ax0, a, c); }
        { float4 a = A3, c = C3; A3 = __ldcs(p1 + 28); C3 = __ldcs(p2 + 28); dot3(aq0, an0, ax0, a, c); }
        { float4 a = A0, c = C0; A0 = __ldcs(np1 +  0); C0 = __ldcs(np2 +  0); dot3(aq1, an1, ax1, a, c); }
        { float4 a = A1, c = C1; A1 = __ldcs(np1 +  4); C1 = __ldcs(np2 +  4); dot3(aq1, an1, ax1, a, c); }
        { float4 a = A2, c = C2; A2 = __ldcs(np1 +  8); C2 = __ldcs(np2 +  8); dot3(aq1, an1, ax1, a, c); }
        { float4 a = A3, c = C3; A3 = __ldcs(np1 + 12); C3 = __ldcs(np2 + 12); dot3(aq1, an1, ax1, a, c); }

        #pragma unroll
        for (int m = 1; m < 4; m <<= 1) {
            aq0 += __shfl_xor_sync(0xffffffffu, aq0, m);
            an0 += __shfl_xor_sync(0xffffffffu, an0, m);
            ax0 += __shfl_xor_sync(0xffffffffu, ax0, m);
            aq1 += __shfl_xor_sync(0xffffffffu, aq1, m);
            an1 += __shfl_xor_sync(0xffffffffu, an1, m);
            ax1 += __shfl_xor_sync(0xffffffffu, ax1, m);
        }
        if (c4 == 0) {
            sv[i * SIMD + 2 * g]     = ax0 / ((sqrtf(aq0) + 1e-8f) * (sqrtf(an0) + 1e-8f));
            sv[i * SIMD + 2 * g + 1] = ax1 / ((sqrtf(aq1) + 1e-8f) * (sqrtf(an1) + 1e-8f));
        }
        p1 = np1; p2 = np2;
    }
    __syncthreads();

    // ---- fused tail over the 12 local rows; accumulate into out[b] ----
    float part = 0.f;
    #pragma unroll
    for (int qq = 0; qq < 3; qq++) {
        const int p = tid + qq * 128;      // 0..383 = 12 rows x 32 hh
        const int i = p >> 5, hh = p & 31;
        float acc = b1s[hh];
        #pragma unroll
        for (int d = 0; d < SIMD; d++)
            acc = fmaf(sv[i * SIMD + d], W1fs[d * HIDD + hh], acc);
        part = fmaf(w2ss[hh], tanhf(acc), part);
    }
    #pragma unroll
    for (int m = 1; m < 32; m <<= 1)
        part += __shfl_xor_sync(0xffffffffu, part, m);
    if (lane == 0) red[w] = part;
    __syncthreads();
    if (tid == 0)
        atomicAdd(&out[b], red[0] + red[1] + red[2] + red[3]);
}

extern "C" void kernel_launch(void* const* d_in, const int* in_sizes, int n_in,
                              void* d_out, int out_size) {
    const int Bn = in_sizes[0] / (NREG * EMBD);
    prep_kernel<<<1, 512>>>((const float*)d_in[4], (const float*)d_in[5],
                            (const float*)d_in[6], (const float*)d_in[7],
                            (const float*)d_in[8], (const float*)d_in[9],
                            (const float*)d_in[10], (float*)d_out, Bn);
    dim3 grid(3, Bn);
    simgsmn_main<<<grid, 128>>>((const float*)d_in[0], (const float*)d_in[1], (float*)d_out);
}

// round 13
// speedup vs baseline: 1.1547x; 1.1547x over previous
#include <cuda_runtime.h>
#include <math.h>

#define NREG 36
#define EMBD 1024
#define SIMD 16
#define HIDD 32
#define NKER 8
#define GRID 1332           // 9 CTAs/SM * 148 SMs
#define NWARP (GRID * 4)    // 5328 streaming warps

// Precomputed folded constants (prep_kernel -> main kernel)
__device__ float g_W1f[SIMD * HIDD];  // gsum · w1n^T folded: [d][hh]
__device__ float g_w2s[HIDD];         // weight-normed out2 row / 36
__device__ float g_b1[HIDD];

__global__ void prep_kernel(const float* __restrict__ gcn_w,
                            const float* __restrict__ out1_v, const float* __restrict__ out1_g,
                            const float* __restrict__ out1_b, const float* __restrict__ out2_v,
                            const float* __restrict__ out2_g, const float* __restrict__ out2_b,
                            float* __restrict__ out, int Bn)
{
    __shared__ float gs[SIMD * HIDD];
    __shared__ float w1[HIDD * HIDD];
    __shared__ float b2v;
    const int tid = threadIdx.x;  // 512
    {
        float a = 0.f;
        #pragma unroll
        for (int k = 0; k < NKER; k++) a += gcn_w[k * SIMD * HIDD + tid];
        gs[tid] = a;
    }
    if (tid < HIDD) {
        float ss = 0.f;
        #pragma unroll
        for (int h = 0; h < HIDD; h++) { float v = out1_v[tid * HIDD + h]; ss += v * v; }
        const float sc = out1_g[tid] / (sqrtf(ss) + 1e-12f);
        #pragma unroll
        for (int h = 0; h < HIDD; h++) w1[tid * HIDD + h] = out1_v[tid * HIDD + h] * sc;
        g_b1[tid] = out1_b[tid];
    }
    if (tid == 32) {
        float ss = 0.f;
        #pragma unroll
        for (int h = 0; h < HIDD; h++) { float v = out2_v[h]; ss += v * v; }
        const float sc = out2_g[0] / (sqrtf(ss) + 1e-12f);
        #pragma unroll
        for (int h = 0; h < HIDD; h++) g_w2s[h] = out2_v[h] * sc * (1.0f / 36.0f);
        b2v = out2_b[0];
    }
    __syncthreads();
    {
        const int d = tid >> 5, hh = tid & 31;
        float acc = 0.f;
        #pragma unroll
        for (int h = 0; h < HIDD; h++)
            acc = fmaf(gs[d * HIDD + h], w1[hh * HIDD + h], acc);
        g_W1f[d * HIDD + hh] = acc;
    }
    // init out[b] = b2; row scores accumulate on top via atomicAdd
    for (int i = tid; i < Bn; i += 512) out[i] = b2v;
}

__device__ __forceinline__ void dot3(float& q, float& n, float& x, const float4 a, const float4 c) {
    q = fmaf(a.x, a.x, q); q = fmaf(a.y, a.y, q); q = fmaf(a.z, a.z, q); q = fmaf(a.w, a.w, q);
    n = fmaf(c.x, c.x, n); n = fmaf(c.y, c.y, n); n = fmaf(c.z, c.z, n); n = fmaf(c.w, c.w, n);
    x = fmaf(a.x, c.x, x); x = fmaf(a.y, c.y, x); x = fmaf(a.z, c.z, x); x = fmaf(a.w, c.w, x);
}

// Persistent row-streaming: warps stream global rows (stride NWARP) through the
// R5 depth-4 pipeline continuously; per-row score computed inline (overlapping
// the next row's in-flight loads) and atomically accumulated into out[row/36].
// No barriers, no wave structure, no per-batch phases.
__global__ void __launch_bounds__(128, 9)
simgsmn_main(const float* __restrict__ inp1, const float* __restrict__ inp2,
             float* __restrict__ out, int totRows)
{
    __shared__ float W1fs[SIMD * HIDD];
    __shared__ float w2ss[HIDD];
    __shared__ float b1s[HIDD];
    const int tid  = threadIdx.x;
    const int w    = tid >> 5;
    const int lane = tid & 31;
    const int g    = lane >> 2;     // group owns sim blocks {2g, 2g+1}
    const int c4   = lane & 3;

    #pragma unroll
    for (int r = 0; r < 4; r++) W1fs[tid + r * 128] = g_W1f[tid + r * 128];
    if (tid < HIDD) { w2ss[tid] = g_w2s[tid]; b1s[tid] = g_b1[tid]; }
    __syncthreads();

    int r = blockIdx.x * 4 + w;                       // this warp's first global row
    if (r >= totRows) return;                         // (whole warp uniform)
    const int loff = g * 32 + c4;                     // lane slot within a row (float4 units)
    const float4* p1 = reinterpret_cast<const float4*>(inp1) + (size_t)r * 256 + loff;
    const float4* p2 = reinterpret_cast<const float4*>(inp2) + (size_t)r * 256 + loff;

    // prologue: first row's first half in flight
    float4 A0 = __ldcs(p1 +  0), C0 = __ldcs(p2 +  0);
    float4 A1 = __ldcs(p1 +  4), C1 = __ldcs(p2 +  4);
    float4 A2 = __ldcs(p1 +  8), C2 = __ldcs(p2 +  8);
    float4 A3 = __ldcs(p1 + 12), C3 = __ldcs(p2 + 12);

    #pragma unroll 1
    while (r < totRows) {
        // advance to next assigned row (clamp on last: reload current, discard)
        const size_t adv = (r + NWARP < totRows) ? (size_t)NWARP * 256 : 0;
        float aq0 = 0.f, an0 = 0.f, ax0 = 0.f, aq1 = 0.f, an1 = 0.f, ax1 = 0.f;

        { float4 a = A0, c = C0; A0 = __ldcs(p1 + 16); C0 = __ldcs(p2 + 16); dot3(aq0, an0, ax0, a, c); }
        { float4 a = A1, c = C1; A1 = __ldcs(p1 + 20); C1 = __ldcs(p2 + 20); dot3(aq0, an0, ax0, a, c); }
        { float4 a = A2, c = C2; A2 = __ldcs(p1 + 24); C2 = __ldcs(p2 + 24); dot3(aq0, an0, ax0, a, c); }
        { float4 a = A3, c = C3; A3 = __ldcs(p1 + 28); C3 = __ldcs(p2 + 28); dot3(aq0, an0, ax0, a, c); }
        { float4 a = A0, c = C0; A0 = __ldcs(p1 + adv +  0); C0 = __ldcs(p2 + adv +  0); dot3(aq1, an1, ax1, a, c); }
        { float4 a = A1, c = C1; A1 = __ldcs(p1 + adv +  4); C1 = __ldcs(p2 + adv +  4); dot3(aq1, an1, ax1, a, c); }
        { float4 a = A2, c = C2; A2 = __ldcs(p1 + adv +  8); C2 = __ldcs(p2 + adv +  8); dot3(aq1, an1, ax1, a, c); }
        { float4 a = A3, c = C3; A3 = __ldcs(p1 + adv + 12); C3 = __ldcs(p2 + adv + 12); dot3(aq1, an1, ax1, a, c); }

        // reduce within 4-lane group
        #pragma unroll
        for (int m = 1; m < 4; m <<= 1) {
            aq0 += __shfl_xor_sync(0xffffffffu, aq0, m);
            an0 += __shfl_xor_sync(0xffffffffu, an0, m);
            ax0 += __shfl_xor_sync(0xffffffffu, ax0, m);
            aq1 += __shfl_xor_sync(0xffffffffu, aq1, m);
            an1 += __shfl_xor_sync(0xffffffffu, an1, m);
            ax1 += __shfl_xor_sync(0xffffffffu, ax1, m);
        }
        // normalized sim values for this row (valid on every lane of the group)
        const float sv0 = ax0 / ((sqrtf(aq0) + 1e-8f) * (sqrtf(an0) + 1e-8f));
        const float sv1 = ax1 / ((sqrtf(aq1) + 1e-8f) * (sqrtf(an1) + 1e-8f));

        // ---- inline per-row tail (overlaps next row's loads) ----
        // lane = hh; gather the 16 sv values via broadcast shuffles
        float acc = b1s[lane];
        #pragma unroll
        for (int d = 0; d < SIMD; d++) {
            const float v = __shfl_sync(0xffffffffu, (d & 1) ? sv1 : sv0, (d >> 1) << 2);
            acc = fmaf(v, W1fs[d * HIDD + lane], acc);
        }
        float part = w2ss[lane] * tanhf(acc);
        #pragma unroll
        for (int m = 1; m < 32; m <<= 1)
            part += __shfl_xor_sync(0xffffffffu, part, m);
        if (lane == 0) atomicAdd(&out[r / NREG], part);

        p1 += adv; p2 += adv;
        r  += NWARP;
    }
}

extern "C" void kernel_launch(void* const* d_in, const int* in_sizes, int n_in,
                              void* d_out, int out_size) {
    const int Bn = in_sizes[0] / (NREG * EMBD);
    const int totRows = Bn * NREG;
    prep_kernel<<<1, 512>>>((const float*)d_in[4], (const float*)d_in[5],
                            (const float*)d_in[6], (const float*)d_in[7],
                            (const float*)d_in[8], (const float*)d_in[9],
                            (const float*)d_in[10], (float*)d_out, Bn);
    const int grid = (GRID * 4 <= totRows) ? GRID : (totRows + 3) / 4;
    simgsmn_main<<<grid, 128>>>((const float*)d_in[0], (const float*)d_in[1],
                                (float*)d_out, totRows);
}